// round 9
// baseline (speedup 1.0000x reference)
#include <cuda_runtime.h>
#include <cstdint>

// ASG loss = FCC (log-partition over all paths) - FAC (forced alignment).
// T=512, B=32, V=512, L=128 (fixed by dataset).
//
// FCC: unnormalized probability recursion v' = exp(lp) * (E v), E in regs.
// Cluster of 8 CTAs per 2 batches. The two batches form DECOUPLED exchange
// chains: per step, each warp computes batch 0's 4 row-dots, pushes them
// (scalar 4B self-signaling st.async to all 8 ranks), then batch 1 ditto.
// Separate mbarriers per (batch, buffer) [4 total, expect_tx = 2048B] let
// batch-1 flight hide under batch-0 compute and absorb inter-CTA skew.
// Row sums land on push lanes {0,8,16,24} via a 6-shuffle merge tree.
// FAC: separate CTAs, 1 warp/batch, register-resident. Output fused via
// per-batch parity atomic.

namespace {
constexpr int T_ = 512, B_ = 32, V_ = 512, L_ = 128;
constexpr int CSZ = 8;      // cluster size
constexpr int ISL = 64;     // i-rows per CTA
constexpr int NTHR = 512;
constexpr int NFCC = 16;    // FCC clusters (2 batches each)
constexpr float NEG = -1000000000.0f;
constexpr unsigned FILL_BYTES = V_ * 4u;   // 2048 B per (batch) fill
}

__device__ float g_fcc[B_];
__device__ float g_fac[B_];
__device__ unsigned g_done[B_];   // parity counter, never reset

static __device__ __forceinline__ unsigned cta_rank() {
    unsigned r; asm("mov.u32 %0, %%cluster_ctarank;" : "=r"(r)); return r;
}
static __device__ __forceinline__ unsigned su32(const void* p) {
    unsigned a;
    asm("{ .reg .u64 t; cvta.to.shared.u64 t, %1; cvt.u32.u64 %0, t; }"
        : "=r"(a) : "l"(p));
    return a;
}
static __device__ __forceinline__ unsigned mapa_r(unsigned a, unsigned r) {
    unsigned o;
    asm("mapa.shared::cluster.u32 %0, %1, %2;" : "=r"(o) : "r"(a), "r"(r));
    return o;
}
static __device__ __forceinline__ void csync() {
    asm volatile("barrier.cluster.arrive.aligned;" ::: "memory");
    asm volatile("barrier.cluster.wait.aligned;" ::: "memory");
}
static __device__ __forceinline__ void mbar_init(unsigned a, unsigned cnt) {
    asm volatile("mbarrier.init.shared.b64 [%0], %1;" :: "r"(a), "r"(cnt) : "memory");
}
static __device__ __forceinline__ void mbar_expect(unsigned a, unsigned tx) {
    asm volatile("mbarrier.arrive.expect_tx.shared.b64 _, [%0], %1;"
                 :: "r"(a), "r"(tx) : "memory");
}
// Self-signaling remote store: data lands in peer SMEM, credits 4 bytes on
// the peer's mbarrier when complete.
static __device__ __forceinline__ void st_async32(unsigned a, float v, unsigned mb) {
    asm volatile("st.async.shared::cluster.mbarrier::complete_tx::bytes.b32 [%0], %1, [%2];"
                 :: "r"(a), "r"(__float_as_uint(v)), "r"(mb) : "memory");
}
static __device__ __forceinline__ void mbar_wait(unsigned a, unsigned parity) {
    unsigned done;
    asm volatile(
        "{\n\t.reg .pred p;\n\t"
        "mbarrier.try_wait.parity.acquire.cluster.shared::cta.b64 p, [%1], %2;\n\t"
        "selp.b32 %0, 1, 0, p;\n\t}"
        : "=r"(done) : "r"(a), "r"(parity) : "memory");
    if (!done) {
        asm volatile(
            "{\n\t.reg .pred P1;\n\t"
            "WL_%=:\n\t"
            "mbarrier.try_wait.parity.acquire.cluster.shared::cta.b64 P1, [%0], %1, 0x989680;\n\t"
            "@P1 bra.uni WD_%=;\n\t"
            "bra.uni WL_%=;\n\t"
            "WD_%=:\n\t}"
            :: "r"(a), "r"(parity) : "memory");
    }
}
static __device__ __forceinline__ unsigned long long fma2(
    unsigned long long a, unsigned long long b, unsigned long long c) {
    unsigned long long d;
    asm("fma.rn.f32x2 %0, %1, %2, %3;" : "=l"(d) : "l"(a), "l"(b), "l"(c));
    return d;
}
static __device__ __forceinline__ unsigned long long packf2(float lo, float hi) {
    unsigned long long d;
    asm("mov.b64 %0, {%1,%2};" : "=l"(d) : "f"(lo), "f"(hi));
    return d;
}
static __device__ __forceinline__ float pairsum(unsigned long long a) {
    float lo, hi;
    asm("mov.b64 {%0,%1}, %2;" : "=f"(lo), "=f"(hi) : "l"(a));
    return lo + hi;
}
// Merge-reduce step: combine two per-lane partial vectors; lanes with
// (lane & m) carry the 'b' index forward.
static __device__ __forceinline__ float mrg(float a, float b, int m, int lane) {
    float send = (lane & m) ? a : b;
    float keep = (lane & m) ? b : a;
    return keep + __shfl_xor_sync(~0u, send, m);
}

// Second arriver (parity odd) of {fcc, fac} writes the output.
static __device__ __forceinline__ void publish(int b, float val, bool is_fcc,
                                               float* __restrict__ out) {
    if (is_fcc) g_fcc[b] = val; else g_fac[b] = val;
    __threadfence();
    unsigned old = atomicAdd(&g_done[b], 1u);
    if (old & 1u) {
        __threadfence();
        out[b] = g_fcc[b] - g_fac[b];
    }
}

__global__ void __launch_bounds__(NTHR, 1) __cluster_dims__(CSZ, 1, 1)
asg_main(const float* __restrict__ lp, const float* __restrict__ tr,
         const int* __restrict__ tgt, const int* __restrict__ ilen,
         const int* __restrict__ tlen, float* __restrict__ out)
{
    __shared__ __align__(16) float s_u[2][2][V_];        // [buf][batch] v
    __shared__ __align__(8) unsigned long long s_mbar[4]; // [batch*2 + buf]

    const int tid  = threadIdx.x;
    const int lane = tid & 31;
    const int wid  = tid >> 5;
    const int cid  = (int)blockIdx.x >> 3;

    if (cid < NFCC) {
        // =============================== FCC ===============================
        const unsigned r = cta_rank();
        const int b0 = 2 * cid, b1 = 2 * cid + 1;
        const int len0 = ilen[b0], len1 = ilen[b1];

        // Push lanes {0,8,16,24}: lane holds the full sum for row
        // wid*4 + (lane>>3) after the 6-shuffle merge tree.
        const bool isp = (lane & 7) == 0;
        const int prow = (int)r * ISL + wid * 4 + (lane >> 3);  // global row

        const unsigned ubase  = su32(&s_u[0][0][0]);
        const unsigned mloc   = su32(&s_mbar[0]);
        const unsigned mdelta = mloc - ubase;
        unsigned pb[CSZ];
        #pragma unroll
        for (int rk = 0; rk < CSZ; ++rk) pb[rk] = mapa_r(ubase, (unsigned)rk);

        if (tid == 0) {
            #pragma unroll
            for (int k = 0; k < 4; ++k) mbar_init(mloc + 8u * k, 1);
            mbar_expect(mloc + 8u * 1, FILL_BYTES);   // (b0, buf1): fill @ t=0
            mbar_expect(mloc + 8u * 3, FILL_BYTES);   // (b1, buf1): fill @ t=0
        }

        // E registers: warp w owns rows r*64 + 4w + rr (rr<4); lane owns
        // j in {4*lane + 128k + m}: conflict-free interleaved map.
        unsigned long long e2[32];
        #pragma unroll
        for (int rr = 0; rr < 4; ++rr) {
            const int row = (int)r * ISL + wid * 4 + rr;
            #pragma unroll
            for (int k = 0; k < 4; ++k) {
                float4 v4 = *(const float4*)(tr + (size_t)row * V_ + 4 * lane + 128 * k);
                e2[rr * 8 + 2 * k]     = packf2(__expf(v4.x), __expf(v4.y));
                e2[rr * 8 + 2 * k + 1] = packf2(__expf(v4.z), __expf(v4.w));
            }
        }

        // v_0 = exp(lp[0,b,:]); every CTA initializes buffer 0 locally.
        s_u[0][0][tid] = __expf(lp[(size_t)b0 * V_ + tid]);
        s_u[0][1][tid] = __expf(lp[(size_t)b1 * V_ + tid]);
        __syncthreads();
        csync();   // peers' mbar init + expect + buffers visible

        // Per-batch half-step: dot 4 rows, merge to push lanes, push.
        auto half = [&](int bs, int buf) {
            unsigned long long acc[4] = {0ull, 0ull, 0ull, 0ull};
            #pragma unroll
            for (int k = 0; k < 4; ++k) {
                ulonglong2 q = *(const ulonglong2*)&s_u[buf][bs][4 * lane + 128 * k];
                #pragma unroll
                for (int rr = 0; rr < 4; ++rr) {
                    acc[rr] = fma2(e2[rr * 8 + 2 * k],     q.x, acc[rr]);
                    acc[rr] = fma2(e2[rr * 8 + 2 * k + 1], q.y, acc[rr]);
                }
            }
            float f0 = pairsum(acc[0]), f1 = pairsum(acc[1]);
            float f2 = pairsum(acc[2]), f3 = pairsum(acc[3]);
            // rows land by lane bits {16,8}: lane0->rr0, lane8->rr1,
            // lane16->rr2, lane24->rr3
            float g0 = mrg(f0, f2, 16, lane);
            float g1 = mrg(f1, f3, 16, lane);
            float h  = mrg(g0, g1, 8, lane);
            h += __shfl_xor_sync(~0u, h, 4);
            h += __shfl_xor_sync(~0u, h, 2);
            h += __shfl_xor_sync(~0u, h, 1);
            return h;   // valid on push lanes
        };

        for (int t = 0; t < T_; ++t) {
            const int buf = t & 1;
            const unsigned par = (unsigned)(((t - 1) >> 1) & 1);

            // Prefetch exp(lp[t+1]) for this push lane's row, both batches
            float el0 = 0.f, el1 = 0.f;
            if (isp && t + 1 < T_) {
                el0 = __expf(lp[((size_t)(t + 1) * B_ + b0) * V_ + prow]);
                el1 = __expf(lp[((size_t)(t + 1) * B_ + b1) * V_ + prow]);
            }

            // ---------------- batch 0 half ----------------
            if (t) mbar_wait(mloc + 8u * (unsigned)buf, par);
            if (tid == 0 && t + 3 <= T_)
                mbar_expect(mloc + 8u * (unsigned)buf, FILL_BYTES);

            if (r == 0 && wid == 8 && t == len0 - 1) {
                float s = 0.f;
                #pragma unroll
                for (int k = 0; k < 16; ++k) s += s_u[buf][0][lane + 32 * k];
                #pragma unroll
                for (int mk = 16; mk; mk >>= 1) s += __shfl_xor_sync(~0u, s, mk);
                if (lane == 0) publish(b0, logf(s), true, out);
            }

            if (t < T_ - 1) {
                const float h = half(0, buf);
                if (isp) {
                    const float v = el0 * h;
                    const int nbuf = buf ^ 1;
                    const unsigned off = ((unsigned)(nbuf * 2 + 0) * V_ + (unsigned)prow) * 4u;
                    const unsigned mboff = mdelta + 8u * (unsigned)(0 * 2 + nbuf);
                    #pragma unroll
                    for (int rk = 0; rk < CSZ; ++rk)
                        st_async32(pb[rk] + off, v, pb[rk] + mboff);
                }
            }

            // ---------------- batch 1 half ----------------
            if (t) mbar_wait(mloc + 8u * (unsigned)(2 + buf), par);
            if (tid == 0 && t + 3 <= T_)
                mbar_expect(mloc + 8u * (unsigned)(2 + buf), FILL_BYTES);

            if (r == 0 && wid == 9 && t == len1 - 1) {
                float s = 0.f;
                #pragma unroll
                for (int k = 0; k < 16; ++k) s += s_u[buf][1][lane + 32 * k];
                #pragma unroll
                for (int mk = 16; mk; mk >>= 1) s += __shfl_xor_sync(~0u, s, mk);
                if (lane == 0) publish(b1, logf(s), true, out);
            }
            if (t == T_ - 1) break;

            {
                const float h = half(1, buf);
                if (isp) {
                    const float v = el1 * h;
                    const int nbuf = buf ^ 1;
                    const unsigned off = ((unsigned)(nbuf * 2 + 1) * V_ + (unsigned)prow) * 4u;
                    const unsigned mboff = mdelta + 8u * (unsigned)(1 * 2 + nbuf);
                    #pragma unroll
                    for (int rk = 0; rk < CSZ; ++rk)
                        st_async32(pb[rk] + off, v, pb[rk] + mboff);
                }
            }
        }
        csync();   // no CTA exits while peers may still write its SMEM
    } else {
        // =============================== FAC ===============================
        if (wid >= 4) return;
        const int b = ((int)blockIdx.x - NFCC * CSZ) * 4 + wid;   // 0..31
        const int il = ilen[b], tl = tlen[b];

        int tg[4];
        #pragma unroll
        for (int k = 0; k < 4; ++k) tg[k] = tgt[b * L_ + lane * 4 + k];

        float ts[4], tp[4];
        #pragma unroll
        for (int k = 0; k < 4; ++k) ts[k] = tr[tg[k] * V_ + tg[k]];
        const int tprev = __shfl_up_sync(~0u, tg[3], 1);
        tp[0] = tr[tg[0] * V_ + tprev];           // garbage on lane 0, never used
        tp[1] = tr[tg[1] * V_ + tg[0]];
        tp[2] = tr[tg[2] * V_ + tg[1]];
        tp[3] = tr[tg[3] * V_ + tg[2]];

        float beta[4];
        #pragma unroll
        for (int k = 0; k < 4; ++k)
            beta[k] = (lane == 0 && k == 0) ? lp[(size_t)b * V_ + tg[0]] : NEG;

        float emn[4];
        #pragma unroll
        for (int k = 0; k < 4; ++k)
            emn[k] = lp[((size_t)1 * B_ + b) * V_ + tg[k]];

        for (int t = 0; t < T_; ++t) {
            if (t == il - 1) {
                const int lsel = tl - 1;
                if (lane == (lsel >> 2)) publish(b, beta[lsel & 3], false, out);
            }
            if (t == T_ - 1) break;

            float em[4];
            #pragma unroll
            for (int k = 0; k < 4; ++k) em[k] = emn[k];
            if (t + 2 < T_) {
                #pragma unroll
                for (int k = 0; k < 4; ++k)
                    emn[k] = lp[((size_t)(t + 2) * B_ + b) * V_ + tg[k]];
            }

            const float bprev = __shfl_up_sync(~0u, beta[3], 1);
            float prevs[4] = {bprev, beta[0], beta[1], beta[2]};
            #pragma unroll
            for (int k = 0; k < 4; ++k) {
                float stay = beta[k] + ts[k];
                float move = (lane == 0 && k == 0) ? NEG : prevs[k] + tp[k];
                float hi = fmaxf(stay, move);
                float lo = fminf(stay, move);
                beta[k] = em[k] + hi + __logf(1.f + __expf(lo - hi));
            }
        }
    }
}

extern "C" void kernel_launch(void* const* d_in, const int* in_sizes, int n_in,
                              void* d_out, int out_size) {
    const float* lp  = (const float*)d_in[0];
    const float* tr  = (const float*)d_in[1];
    const int*   tgt = (const int*)d_in[2];
    const int*   il  = (const int*)d_in[3];
    const int*   tl  = (const int*)d_in[4];
    (void)in_sizes; (void)n_in; (void)out_size;

    asg_main<<<NFCC * CSZ + CSZ, NTHR>>>(lp, tr, tgt, il, tl, (float*)d_out);
}